// round 8
// baseline (speedup 1.0000x reference)
#include <cuda_runtime.h>
#include <cuda_bf16.h>
#include <math.h>

#define M_TOT 8192
#define DD 512
#define WSZ (3*512*512)   // elements per weight blob

typedef __nv_bfloat16 bf16;

// ---------------- scratch ----------------
__device__ int   g_perm[M_TOT];
__device__ int   g_group[4];
__device__ bf16  g_ndr[M_TOT*DD];        // bf16 nodes
__device__ bf16  g_node_in [M_TOT*DD];
__device__ bf16  g_node_out[M_TOT*DD];
__device__ bf16  g_h_in [M_TOT*DD];
__device__ bf16  g_h_out[M_TOT*DD];
__device__ bf16  g_rn[M_TOT*DD];         // bf16 r*nodes
__device__ float g_z[M_TOT*DD];          // fp32
__device__ bf16  g_w[5*WSZ];             // bf16 W_in,W_out,W_r,W_z,W_t
__device__ bf16  g_p[2*M_TOT*1024];      // bf16 probs (32MB)
__device__ float g_sq[2*M_TOT];
__device__ float g_sv[2*M_TOT];
__device__ float g_eq[2*M_TOT];
__device__ float g_fq[2*M_TOT];
__device__ float g_ev[2*M_TOT];
__device__ float g_fv[2*M_TOT];

// ---------------- helpers ----------------
__device__ __forceinline__ unsigned pk(float a, float b) {
    __nv_bfloat162 t = __floats2bfloat162_rn(a, b);
    return *(unsigned*)&t;
}
__device__ __forceinline__ void mma16(float* c, const unsigned* a, unsigned b0, unsigned b1) {
    asm volatile(
        "mma.sync.aligned.m16n8k16.row.col.f32.bf16.bf16.f32 "
        "{%0,%1,%2,%3}, {%4,%5,%6,%7}, {%8,%9}, {%0,%1,%2,%3};\n"
        : "+f"(c[0]), "+f"(c[1]), "+f"(c[2]), "+f"(c[3])
        : "r"(a[0]), "r"(a[1]), "r"(a[2]), "r"(a[3]), "r"(b0), "r"(b1));
}
__device__ __forceinline__ void ldsm4(unsigned* r, unsigned addr) {
    asm volatile("ldmatrix.sync.aligned.m8n8.x4.shared.b16 {%0,%1,%2,%3}, [%4];"
        : "=r"(r[0]), "=r"(r[1]), "=r"(r[2]), "=r"(r[3]) : "r"(addr));
}
__device__ __forceinline__ void ldsm4t(unsigned* r, unsigned addr) {
    asm volatile("ldmatrix.sync.aligned.m8n8.x4.trans.shared.b16 {%0,%1,%2,%3}, [%4];"
        : "=r"(r[0]), "=r"(r[1]), "=r"(r[2]), "=r"(r[3]) : "r"(addr));
}
__device__ __forceinline__ void cpa16(unsigned dst, const void* src, bool v) {
    int sz = v ? 16 : 0;
    asm volatile("cp.async.cg.shared.global [%0], [%1], 16, %2;\n"
                 :: "r"(dst), "l"(src), "r"(sz));
}
__device__ __forceinline__ void cpa_commit() {
    asm volatile("cp.async.commit_group;\n");
}

// ---------------- prep ----------------
__global__ void k_prep(const int* __restrict__ ntw)
{
    __shared__ int s_flag;
    __shared__ int s_cnt[1024*3];
    __shared__ int s_tot[3];
    int tid = threadIdx.x;
    if (tid == 0) s_flag = 0;
    __syncthreads();
    int bad = 0;
    for (int i = tid; i < 4096; i += 1024)
        if (ntw[2*i+1] != 0) bad = 1;
    if (bad) atomicOr(&s_flag, 1);
    __syncthreads();
    int is64 = (s_flag == 0);

    int tv[8];
    int c0 = 0, c1 = 0, c2 = 0;
    for (int k = 0; k < 8; k++) {
        int idx = tid*8 + k;
        int v = is64 ? ntw[2*idx] : ntw[idx];
        int t = (v >= 2 && v <= 4) ? (v - 2) : -1;
        tv[k] = t;
        if (t == 0) c0++; else if (t == 1) c1++; else if (t == 2) c2++;
    }
    s_cnt[tid*3+0] = c0; s_cnt[tid*3+1] = c1; s_cnt[tid*3+2] = c2;
    __syncthreads();
    if (tid < 3) {
        int run = 0;
        for (int i = 0; i < 1024; i++) {
            int c = s_cnt[i*3+tid]; s_cnt[i*3+tid] = run; run += c;
        }
        s_tot[tid] = run;
    }
    __syncthreads();
    if (tid == 0) {
        g_group[0] = 0;
        g_group[1] = s_tot[0];
        g_group[2] = s_tot[0] + s_tot[1];
        g_group[3] = s_tot[0] + s_tot[1] + s_tot[2];
    }
    int b0 = s_cnt[tid*3+0];
    int b1 = s_tot[0] + s_cnt[tid*3+1];
    int b2 = s_tot[0] + s_tot[1] + s_cnt[tid*3+2];
    for (int k = 0; k < 8; k++) {
        int idx = tid*8 + k;
        int t = tv[k];
        if (t == 0)      g_perm[b0++] = idx;
        else if (t == 1) g_perm[b1++] = idx;
        else if (t == 2) g_perm[b2++] = idx;
    }
}

__global__ void k_zero()   // zero bf16 node_in/out
{
    int i = blockIdx.x * blockDim.x + threadIdx.x;
    float4 zz = make_float4(0.f, 0.f, 0.f, 0.f);
    ((float4*)g_node_in)[i]  = zz;
    ((float4*)g_node_out)[i] = zz;
}

// ---------------- convert nodes + 5 weight blobs to bf16 ----------------
struct CvtSrcs { const float* nodes; const float* w0; const float* w1;
                 const float* w2; const float* w3; const float* w4; };
__global__ void k_cvt_all(CvtSrcs s)
{
    int i = blockIdx.x * blockDim.x + threadIdx.x;   // float4 index
    const int NF4 = M_TOT*DD/4;        // 1048576
    const int WF4 = WSZ/4;             // 196608
    if (i < NF4) {
        float4 v = ((const float4*)s.nodes)[i];
        ((uint2*)g_ndr)[i] = make_uint2(pk(v.x, v.y), pk(v.z, v.w));
    } else {
        int j = i - NF4;
        int wi = j / WF4, off = j % WF4;
        const float* src = (wi==0)?s.w0:(wi==1)?s.w1:(wi==2)?s.w2:(wi==3)?s.w3:s.w4;
        float4 v = ((const float4*)src)[off];
        ((uint2*)g_w)[j] = make_uint2(pk(v.x, v.y), pk(v.z, v.w));
    }
}

// ---------------- per-row dots + factored exps ----------------
__device__ __forceinline__ float dot4(float4 a, float4 b) {
    return a.x*b.x + a.y*b.y + a.z*b.z + a.w*b.w;
}
__device__ __forceinline__ float dotb(uint2 u, float4 b) {
    float2 f0 = __bfloat1622float2(*(__nv_bfloat162*)&u.x);
    float2 f1 = __bfloat1622float2(*(__nv_bfloat162*)&u.y);
    return f0.x*b.x + f0.y*b.y + f1.x*b.z + f1.y*b.w;
}
__global__ void k_dots(const float* __restrict__ nodes,
    const float* __restrict__ aqi, const float* __restrict__ avi,
    const float* __restrict__ aqo, const float* __restrict__ avo)
{
    int row = blockIdx.x, tid = threadIdx.x;
    size_t off = ((size_t)row << 9) + tid*4;
    int d = tid*4;
    float4 nv = *(const float4*)(nodes + off);
    uint2 ni = *(const uint2*)(g_node_in + off);
    uint2 no = *(const uint2*)(g_node_out + off);
    float s0 = dot4(nv, *(const float4*)(aqi + d));
    float s1 = dotb(ni, *(const float4*)(avi + d));
    float s2 = dot4(nv, *(const float4*)(aqo + d));
    float s3 = dotb(no, *(const float4*)(avo + d));
    #pragma unroll
    for (int o2 = 16; o2; o2 >>= 1) {
        s0 += __shfl_down_sync(0xffffffffu, s0, o2);
        s1 += __shfl_down_sync(0xffffffffu, s1, o2);
        s2 += __shfl_down_sync(0xffffffffu, s2, o2);
        s3 += __shfl_down_sync(0xffffffffu, s3, o2);
    }
    __shared__ float sm[4][4];
    int w = tid >> 5, l = tid & 31;
    if (l == 0) { sm[w][0]=s0; sm[w][1]=s1; sm[w][2]=s2; sm[w][3]=s3; }
    __syncthreads();
    if (tid == 0) {
        float r0=0,r1=0,r2=0,r3=0;
        #pragma unroll
        for (int i = 0; i < 4; i++) { r0+=sm[i][0]; r1+=sm[i][1]; r2+=sm[i][2]; r3+=sm[i][3]; }
        g_sq[row] = r0; g_sv[row] = r1;
        g_sq[M_TOT+row] = r2; g_sv[M_TOT+row] = r3;
        g_eq[row] = __expf(r0);        g_fq[row] = __expf(0.2f*r0);
        g_ev[row] = __expf(r1);        g_fv[row] = __expf(0.2f*r1);
        g_eq[M_TOT+row] = __expf(r2);  g_fq[M_TOT+row] = __expf(0.2f*r2);
        g_ev[M_TOT+row] = __expf(r3);  g_fv[M_TOT+row] = __expf(0.2f*r3);
    }
}

// ---------------- P: normalized attention probabilities (bf16) ----------------
__global__ __launch_bounds__(256) void k_p(const int* __restrict__ mask)
{
    int row = blockIdx.x, dir = blockIdx.y;
    int b = row >> 10;
    int tid = threadIdx.x;
    size_t base = ((size_t)(dir*M_TOT + row)) << 10;
    int gi = dir*M_TOT + row;
    float sq = g_sq[gi], Eq = g_eq[gi], Fq = g_fq[gi];
    int jb = dir*M_TOT + (b << 10);
    int4   mv = ((const int4*)(mask + base))[tid];
    float4 sv = ((const float4*)(g_sv + jb))[tid];
    float4 ev = ((const float4*)(g_ev + jb))[tid];
    float4 fv = ((const float4*)(g_fv + jb))[tid];
    float w0 = (mv.x > 0) ? ((sq + sv.x >= 0.f) ? Eq*ev.x : Fq*fv.x) : 0.f;
    float w1 = (mv.y > 0) ? ((sq + sv.y >= 0.f) ? Eq*ev.y : Fq*fv.y) : 0.f;
    float w2 = (mv.z > 0) ? ((sq + sv.z >= 0.f) ? Eq*ev.z : Fq*fv.z) : 0.f;
    float w3 = (mv.w > 0) ? ((sq + sv.w >= 0.f) ? Eq*ev.w : Fq*fv.w) : 0.f;
    float s = w0 + w1 + w2 + w3;
    #pragma unroll
    for (int o = 16; o; o >>= 1) s += __shfl_xor_sync(0xffffffffu, s, o);
    __shared__ float swarp[8];
    __shared__ float sinv;
    if ((tid & 31) == 0) swarp[tid >> 5] = s;
    __syncthreads();
    if (tid < 8) {
        float v = swarp[tid];
        #pragma unroll
        for (int o = 4; o; o >>= 1) v += __shfl_xor_sync(0xffu, v, o);
        if (tid == 0) sinv = 1.f / v;
    }
    __syncthreads();
    float inv = sinv;
    ((uint2*)g_p)[(base >> 2) + tid] =
        make_uint2(pk(w0*inv, w1*inv), pk(w2*inv, w3*inv));
}

// ---------------- bf16 MMA GEMM: K-tile 64, 3-stage cp.async -------------------
// MODE 0: fused typed linear. z=t, N=1024 ([W_in|W_out]). A gathered, C scattered.
// MODE 1: fused gates. N=1024 ([W_r|W_z]). col<512 -> g_rn, else g_z.
// MODE 2: final: out = (1-z)*nodes + z*tanh(.). N=512.
// MODE 3: GAT: h = P @ V per (dir,batch). K=1024, N=512.
#define APITCH 72
#define BPITCH 136
#define A_E (128*APITCH)       // 9216 bf16
#define B_E (64*BPITCH)        // 8704 bf16
#define STG_E (A_E + B_E)      // 17920 bf16 per stage
#define SMEM_BYTES (3*STG_E*2) // 107520 B

template<int MODE>
__global__ __launch_bounds__(512, 2) void k_mma(
    const float* __restrict__ nodes_raw,
    const float* __restrict__ bias_a, const float* __restrict__ bias_b,
    float* __restrict__ Cout)
{
    constexpr int KIT = (MODE==0) ? 8 : (MODE==3) ? 16 : 24;
    extern __shared__ bf16 smem[];
    unsigned sbase = (unsigned)__cvta_generic_to_shared(smem);

    int tid = threadIdx.x;
    int nbase = blockIdx.x * 128;
    int which = nbase >> 9;               // fused-N selector (modes 0/1)
    int ncol  = nbase & 511;              // column within the selected weight
    int ar = tid >> 2, ac = tid & 3;      // A staging: row 0..127, chunks ac*8, ac*8+32
    int br = tid >> 4, bc = tid & 15;     // B staging: k-rows br, br+32
    int zed = blockIdx.z;
    int mbase = blockIdx.y * 128;
    int ge = 1 << 30;
    const bf16* Bp = nullptr;
    const bf16 *pa = nullptr;                                  // MODE 0/3
    const bf16 *sA0 = nullptr, *sA1 = nullptr, *sA2 = nullptr; // MODE 1/2 segs

    if (MODE == 0) {
        int t = zed;
        int gs = g_group[t]; ge = g_group[t+1];
        mbase = gs + blockIdx.y * 128;
        if (mbase >= ge) return;
        Bp = g_w + (size_t)which*WSZ + (size_t)t*DD*DD;
        int r0 = mbase + ar;
        pa = (r0 < ge) ? g_ndr + ((size_t)g_perm[r0] << 9) : nullptr;
    } else if (MODE == 1 || MODE == 2) {
        size_t o0 = (size_t)(mbase + ar) << 9;
        sA0 = g_h_in + o0;
        sA1 = g_h_out + o0;
        sA2 = (MODE == 1 ? g_ndr : g_rn) + o0;
        Bp = g_w + (size_t)((MODE == 1) ? (2 + which) : 4) * WSZ;
    } else { // MODE 3
        int dir = zed >> 3, b = zed & 7;
        pa = g_p + ((size_t)(dir*M_TOT + (b << 10) + mbase + ar) << 10);
        Bp = (dir ? g_node_out : g_node_in) + (((size_t)(b << 10)) << 9);
    }

    auto issue = [&](int kt) {
        unsigned st = (unsigned)((kt % 3) * STG_E);
        unsigned dA = sbase + (st + ar*APITCH + ac*8) * 2;
        if (MODE == 0) {
            const bf16* s0 = pa ? pa + kt*64 + ac*8 : (const bf16*)g_ndr;
            cpa16(dA, s0, pa != nullptr);
            cpa16(dA + 64, pa ? s0 + 32 : (const bf16*)g_ndr, pa != nullptr);
        } else if (MODE == 3) {
            const bf16* s0 = pa + kt*64 + ac*8;
            cpa16(dA, s0, true);
            cpa16(dA + 64, s0 + 32, true);
        } else {
            int seg = kt >> 3;
            int off = (kt & 7)*64 + ac*8;
            const bf16* sb = ((seg == 0) ? sA0 : (seg == 1) ? sA1 : sA2) + off;
            cpa16(dA, sb, true);
            cpa16(dA + 64, sb + 32, true);
        }
        unsigned dB = sbase + (st + A_E + br*BPITCH + bc*8) * 2;
        const bf16* sB = Bp + (size_t)(kt*64 + br)*DD + ncol + bc*8;
        cpa16(dB, sB, true);
        cpa16(dB + 32*BPITCH*2, sB + (size_t)32*DD, true);
    };

    // fragment lane decomposition
    int lane = tid & 31, wid = tid >> 5;
    int wm = (wid >> 2) * 32, wn = (wid & 3) * 32;
    int q = lane >> 3, li = lane & 7;
    int arow_f = li + (q & 1)*8;
    int acol_f = (q >> 1)*8;
    int g = lane >> 2, tg = lane & 3;

    float acc[2][4][4];
    #pragma unroll
    for (int mi = 0; mi < 2; mi++)
        #pragma unroll
        for (int ni = 0; ni < 4; ni++)
            #pragma unroll
            for (int qq = 0; qq < 4; qq++) acc[mi][ni][qq] = 0.f;

    issue(0); cpa_commit();
    issue(1); cpa_commit();

    for (int kt = 0; kt < KIT; kt++) {
        asm volatile("cp.async.wait_group 1;\n");
        __syncthreads();
        if (kt + 2 < KIT) issue(kt + 2);
        cpa_commit();

        unsigned As = sbase + (unsigned)((kt % 3) * STG_E) * 2;
        unsigned Bs = As + A_E * 2;
        #pragma unroll
        for (int ks = 0; ks < 64; ks += 16) {
            unsigned a[2][4], bfr[2][4];
            #pragma unroll
            for (int mi = 0; mi < 2; mi++)
                ldsm4(a[mi], As + ((wm + mi*16 + arow_f)*APITCH + ks + acol_f) * 2);
            #pragma unroll
            for (int n2 = 0; n2 < 2; n2++)
                ldsm4t(bfr[n2], Bs + ((ks + arow_f)*BPITCH + wn + n2*16 + acol_f) * 2);
            #pragma unroll
            for (int mi = 0; mi < 2; mi++)
                #pragma unroll
                for (int ni = 0; ni < 4; ni++)
                    mma16(acc[mi][ni], a[mi], bfr[ni>>1][(ni&1)*2], bfr[ni>>1][(ni&1)*2+1]);
        }
    }

    // ---- epilogue
    bf16* CbM0 = (MODE == 0) ? (which ? g_node_out : g_node_in) : nullptr;
    bf16* CbM3 = nullptr;
    if (MODE == 3) {
        int dir = zed >> 3, b = zed & 7;
        CbM3 = (dir ? g_h_out : g_h_in) + (((size_t)(b << 10)) << 9);
    }
    #pragma unroll
    for (int mi = 0; mi < 2; mi++) {
        int rA = mbase + wm + mi*16 + g;
        int rB = rA + 8;
        int pA = rA, pB = rB;
        if (MODE == 0) {
            pA = (rA < ge) ? g_perm[rA] : -1;
            pB = (rB < ge) ? g_perm[rB] : -1;
        }
        #pragma unroll
        for (int ni = 0; ni < 4; ni++) {
            int lcol = ncol + wn + ni*8 + 2*tg;   // column within 512-wide output
            float c0 = acc[mi][ni][0], c1 = acc[mi][ni][1];
            float c2 = acc[mi][ni][2], c3 = acc[mi][ni][3];
            if (MODE == 0) {
                if (pA >= 0) *(unsigned*)&CbM0[((size_t)pA << 9) + lcol] = pk(c0, c1);
                if (pB >= 0) *(unsigned*)&CbM0[((size_t)pB << 9) + lcol] = pk(c2, c3);
            } else if (MODE == 1) {
                size_t oA = ((size_t)pA << 9) + lcol, oB = ((size_t)pB << 9) + lcol;
                float2 bb = *(const float2*)&((which == 0) ? bias_a : bias_b)[lcol];
                float s0 = 1.f/(1.f + __expf(-(c0 + bb.x)));
                float s1 = 1.f/(1.f + __expf(-(c1 + bb.y)));
                float s2 = 1.f/(1.f + __expf(-(c2 + bb.x)));
                float s3 = 1.f/(1.f + __expf(-(c3 + bb.y)));
                if (which == 0) {
                    float2 nA = *(const float2*)&nodes_raw[oA];
                    float2 nB = *(const float2*)&nodes_raw[oB];
                    *(unsigned*)&g_rn[oA] = pk(s0*nA.x, s1*nA.y);
                    *(unsigned*)&g_rn[oB] = pk(s2*nB.x, s3*nB.y);
                } else {
                    *(float2*)&g_z[oA] = make_float2(s0, s1);
                    *(float2*)&g_z[oB] = make_float2(s2, s3);
                }
            } else if (MODE == 2) {
                float2 bb = *(const float2*)&bias_a[lcol];
                size_t oA = ((size_t)pA << 9) + lcol, oB = ((size_t)pB << 9) + lcol;
                float2 zA = *(const float2*)&g_z[oA], zB = *(const float2*)&g_z[oB];
                float2 nA = *(const float2*)&nodes_raw[oA], nB = *(const float2*)&nodes_raw[oB];
                float h0 = tanhf(c0 + bb.x), h1 = tanhf(c1 + bb.y);
                float h2 = tanhf(c2 + bb.x), h3 = tanhf(c3 + bb.y);
                *(float2*)&Cout[oA] = make_float2((1.f-zA.x)*nA.x + zA.x*h0,
                                                  (1.f-zA.y)*nA.y + zA.y*h1);
                *(float2*)&Cout[oB] = make_float2((1.f-zB.x)*nB.x + zB.x*h2,
                                                  (1.f-zB.y)*nB.y + zB.y*h3);
            } else { // MODE 3
                *(unsigned*)&CbM3[((size_t)pA << 9) + lcol] = pk(c0, c1);
                *(unsigned*)&CbM3[((size_t)pB << 9) + lcol] = pk(c2, c3);
            }
        }
    }
}

// ---------------- launch ----------------
extern "C" void kernel_launch(void* const* d_in, const int* in_sizes, int n_in,
                              void* d_out, int out_size)
{
    const float* nodes  = (const float*)d_in[0];
    const int*   mask   = (const int*)  d_in[1];
    const int*   ntw    = (const int*)  d_in[2];
    const float* W_in   = (const float*)d_in[3];
    const float* W_out  = (const float*)d_in[4];
    const float* a_in_q = (const float*)d_in[5];
    const float* a_in_v = (const float*)d_in[6];
    const float* a_out_q= (const float*)d_in[7];
    const float* a_out_v= (const float*)d_in[8];
    const float* W_r    = (const float*)d_in[9];
    const float* b_r    = (const float*)d_in[10];
    const float* W_z    = (const float*)d_in[11];
    const float* b_z    = (const float*)d_in[12];
    const float* W_t    = (const float*)d_in[13];
    const float* b_t    = (const float*)d_in[14];
    float* out = (float*)d_out;

    cudaFuncSetAttribute(k_mma<0>, cudaFuncAttributeMaxDynamicSharedMemorySize, SMEM_BYTES);
    cudaFuncSetAttribute(k_mma<1>, cudaFuncAttributeMaxDynamicSharedMemorySize, SMEM_BYTES);
    cudaFuncSetAttribute(k_mma<2>, cudaFuncAttributeMaxDynamicSharedMemorySize, SMEM_BYTES);
    cudaFuncSetAttribute(k_mma<3>, cudaFuncAttributeMaxDynamicSharedMemorySize, SMEM_BYTES);

    k_prep<<<1, 1024>>>(ntw);
    k_zero<<<2048, 256>>>();
    CvtSrcs cs = { nodes, W_in, W_out, W_r, W_z, W_t };
    k_cvt_all<<<7936, 256>>>(cs);
    k_mma<0><<<dim3(8, 64, 3), 512, SMEM_BYTES>>>(nodes, nullptr, nullptr, nullptr);
    k_dots<<<M_TOT, 128>>>(nodes, a_in_q, a_in_v, a_out_q, a_out_v);
    k_p<<<dim3(M_TOT, 2), 256>>>(mask);
    k_mma<3><<<dim3(4, 8, 16), 512, SMEM_BYTES>>>(nodes, nullptr, nullptr, nullptr);
    k_mma<1><<<dim3(8, 64, 1), 512, SMEM_BYTES>>>(nodes, b_r, b_z, nullptr);
    k_mma<2><<<dim3(4, 64, 1), 512, SMEM_BYTES>>>(nodes, b_t, nullptr, out);
}

// round 11
// speedup vs baseline: 1.5759x; 1.5759x over previous
#include <cuda_runtime.h>
#include <cuda_bf16.h>
#include <math.h>

#define M_TOT 8192
#define DD 512
#define WSZ (3*512*512)   // elements per weight blob

typedef __nv_bfloat16 bf16;

// ---------------- scratch ----------------
__device__ int   g_perm[M_TOT];
__device__ int   g_group[4];
__device__ bf16  g_ndr[M_TOT*DD];        // bf16 nodes
__device__ bf16  g_node_in [M_TOT*DD];
__device__ bf16  g_node_out[M_TOT*DD];
__device__ bf16  g_h_in [M_TOT*DD];
__device__ bf16  g_h_out[M_TOT*DD];
__device__ bf16  g_rn[M_TOT*DD];         // bf16 r*nodes
__device__ float g_z[M_TOT*DD];          // fp32
__device__ bf16  g_w[5*WSZ];             // bf16 W_in,W_out,W_r,W_z,W_t
__device__ bf16  g_p[2*M_TOT*1024];      // bf16 probs (32MB)
__device__ float g_sq[2*M_TOT];
__device__ float g_sv[2*M_TOT];
__device__ float g_eq[2*M_TOT];
__device__ float g_fq[2*M_TOT];
__device__ float g_ev[2*M_TOT];
__device__ float g_fv[2*M_TOT];

// ---------------- helpers ----------------
__device__ __forceinline__ unsigned pk(float a, float b) {
    __nv_bfloat162 t = __floats2bfloat162_rn(a, b);
    return *(unsigned*)&t;
}
__device__ __forceinline__ void mma16(float* c, const unsigned* a, unsigned b0, unsigned b1) {
    asm volatile(
        "mma.sync.aligned.m16n8k16.row.col.f32.bf16.bf16.f32 "
        "{%0,%1,%2,%3}, {%4,%5,%6,%7}, {%8,%9}, {%0,%1,%2,%3};\n"
        : "+f"(c[0]), "+f"(c[1]), "+f"(c[2]), "+f"(c[3])
        : "r"(a[0]), "r"(a[1]), "r"(a[2]), "r"(a[3]), "r"(b0), "r"(b1));
}
__device__ __forceinline__ void ldsm4(unsigned* r, unsigned addr) {
    asm volatile("ldmatrix.sync.aligned.m8n8.x4.shared.b16 {%0,%1,%2,%3}, [%4];"
        : "=r"(r[0]), "=r"(r[1]), "=r"(r[2]), "=r"(r[3]) : "r"(addr));
}
__device__ __forceinline__ void ldsm4t(unsigned* r, unsigned addr) {
    asm volatile("ldmatrix.sync.aligned.m8n8.x4.trans.shared.b16 {%0,%1,%2,%3}, [%4];"
        : "=r"(r[0]), "=r"(r[1]), "=r"(r[2]), "=r"(r[3]) : "r"(addr));
}
__device__ __forceinline__ void cpa16(unsigned dst, const void* src, bool v) {
    int sz = v ? 16 : 0;
    asm volatile("cp.async.cg.shared.global [%0], [%1], 16, %2;\n"
                 :: "r"(dst), "l"(src), "r"(sz));
}
__device__ __forceinline__ void cpa_commit() {
    asm volatile("cp.async.commit_group;\n");
}

// ---------------- prep ----------------
__global__ void k_prep(const int* __restrict__ ntw)
{
    __shared__ int s_flag;
    __shared__ int s_cnt[1024*3];
    __shared__ int s_tot[3];
    int tid = threadIdx.x;
    if (tid == 0) s_flag = 0;
    __syncthreads();
    int bad = 0;
    for (int i = tid; i < 4096; i += 1024)
        if (ntw[2*i+1] != 0) bad = 1;
    if (bad) atomicOr(&s_flag, 1);
    __syncthreads();
    int is64 = (s_flag == 0);

    int tv[8];
    int c0 = 0, c1 = 0, c2 = 0;
    for (int k = 0; k < 8; k++) {
        int idx = tid*8 + k;
        int v = is64 ? ntw[2*idx] : ntw[idx];
        int t = (v >= 2 && v <= 4) ? (v - 2) : -1;
        tv[k] = t;
        if (t == 0) c0++; else if (t == 1) c1++; else if (t == 2) c2++;
    }
    s_cnt[tid*3+0] = c0; s_cnt[tid*3+1] = c1; s_cnt[tid*3+2] = c2;
    __syncthreads();
    if (tid < 3) {
        int run = 0;
        for (int i = 0; i < 1024; i++) {
            int c = s_cnt[i*3+tid]; s_cnt[i*3+tid] = run; run += c;
        }
        s_tot[tid] = run;
    }
    __syncthreads();
    if (tid == 0) {
        g_group[0] = 0;
        g_group[1] = s_tot[0];
        g_group[2] = s_tot[0] + s_tot[1];
        g_group[3] = s_tot[0] + s_tot[1] + s_tot[2];
    }
    int b0 = s_cnt[tid*3+0];
    int b1 = s_tot[0] + s_cnt[tid*3+1];
    int b2 = s_tot[0] + s_tot[1] + s_cnt[tid*3+2];
    for (int k = 0; k < 8; k++) {
        int idx = tid*8 + k;
        int t = tv[k];
        if (t == 0)      g_perm[b0++] = idx;
        else if (t == 1) g_perm[b1++] = idx;
        else if (t == 2) g_perm[b2++] = idx;
    }
}

__global__ void k_zero()   // zero bf16 node_in/out
{
    int i = blockIdx.x * blockDim.x + threadIdx.x;
    float4 zz = make_float4(0.f, 0.f, 0.f, 0.f);
    ((float4*)g_node_in)[i]  = zz;
    ((float4*)g_node_out)[i] = zz;
}

// ---------------- convert nodes + 5 weight blobs to bf16 ----------------
struct CvtSrcs { const float* nodes; const float* w0; const float* w1;
                 const float* w2; const float* w3; const float* w4; };
__global__ void k_cvt_all(CvtSrcs s)
{
    int i = blockIdx.x * blockDim.x + threadIdx.x;   // float4 index
    const int NF4 = M_TOT*DD/4;        // 1048576
    const int WF4 = WSZ/4;             // 196608
    if (i < NF4) {
        float4 v = ((const float4*)s.nodes)[i];
        ((uint2*)g_ndr)[i] = make_uint2(pk(v.x, v.y), pk(v.z, v.w));
    } else {
        int j = i - NF4;
        int wi = j / WF4, off = j % WF4;
        const float* src = (wi==0)?s.w0:(wi==1)?s.w1:(wi==2)?s.w2:(wi==3)?s.w3:s.w4;
        float4 v = ((const float4*)src)[off];
        ((uint2*)g_w)[j] = make_uint2(pk(v.x, v.y), pk(v.z, v.w));
    }
}

// ---------------- per-row dots + factored exps ----------------
__device__ __forceinline__ float dot4(float4 a, float4 b) {
    return a.x*b.x + a.y*b.y + a.z*b.z + a.w*b.w;
}
__device__ __forceinline__ float dotb(uint2 u, float4 b) {
    float2 f0 = __bfloat1622float2(*(__nv_bfloat162*)&u.x);
    float2 f1 = __bfloat1622float2(*(__nv_bfloat162*)&u.y);
    return f0.x*b.x + f0.y*b.y + f1.x*b.z + f1.y*b.w;
}
__global__ void k_dots(const float* __restrict__ nodes,
    const float* __restrict__ aqi, const float* __restrict__ avi,
    const float* __restrict__ aqo, const float* __restrict__ avo)
{
    int row = blockIdx.x, tid = threadIdx.x;
    size_t off = ((size_t)row << 9) + tid*4;
    int d = tid*4;
    float4 nv = *(const float4*)(nodes + off);
    uint2 ni = *(const uint2*)(g_node_in + off);
    uint2 no = *(const uint2*)(g_node_out + off);
    float s0 = dot4(nv, *(const float4*)(aqi + d));
    float s1 = dotb(ni, *(const float4*)(avi + d));
    float s2 = dot4(nv, *(const float4*)(aqo + d));
    float s3 = dotb(no, *(const float4*)(avo + d));
    #pragma unroll
    for (int o2 = 16; o2; o2 >>= 1) {
        s0 += __shfl_down_sync(0xffffffffu, s0, o2);
        s1 += __shfl_down_sync(0xffffffffu, s1, o2);
        s2 += __shfl_down_sync(0xffffffffu, s2, o2);
        s3 += __shfl_down_sync(0xffffffffu, s3, o2);
    }
    __shared__ float sm[4][4];
    int w = tid >> 5, l = tid & 31;
    if (l == 0) { sm[w][0]=s0; sm[w][1]=s1; sm[w][2]=s2; sm[w][3]=s3; }
    __syncthreads();
    if (tid == 0) {
        float r0=0,r1=0,r2=0,r3=0;
        #pragma unroll
        for (int i = 0; i < 4; i++) { r0+=sm[i][0]; r1+=sm[i][1]; r2+=sm[i][2]; r3+=sm[i][3]; }
        g_sq[row] = r0; g_sv[row] = r1;
        g_sq[M_TOT+row] = r2; g_sv[M_TOT+row] = r3;
        g_eq[row] = __expf(r0);        g_fq[row] = __expf(0.2f*r0);
        g_ev[row] = __expf(r1);        g_fv[row] = __expf(0.2f*r1);
        g_eq[M_TOT+row] = __expf(r2);  g_fq[M_TOT+row] = __expf(0.2f*r2);
        g_ev[M_TOT+row] = __expf(r3);  g_fv[M_TOT+row] = __expf(0.2f*r3);
    }
}

// ---------------- P: normalized attention probabilities (bf16) ----------------
__global__ __launch_bounds__(256) void k_p(const int* __restrict__ mask)
{
    int row = blockIdx.x, dir = blockIdx.y;
    int b = row >> 10;
    int tid = threadIdx.x;
    size_t base = ((size_t)(dir*M_TOT + row)) << 10;
    int gi = dir*M_TOT + row;
    float sq = g_sq[gi], Eq = g_eq[gi], Fq = g_fq[gi];
    int jb = dir*M_TOT + (b << 10);
    int4   mv = ((const int4*)(mask + base))[tid];
    float4 sv = ((const float4*)(g_sv + jb))[tid];
    float4 ev = ((const float4*)(g_ev + jb))[tid];
    float4 fv = ((const float4*)(g_fv + jb))[tid];
    float w0 = (mv.x > 0) ? ((sq + sv.x >= 0.f) ? Eq*ev.x : Fq*fv.x) : 0.f;
    float w1 = (mv.y > 0) ? ((sq + sv.y >= 0.f) ? Eq*ev.y : Fq*fv.y) : 0.f;
    float w2 = (mv.z > 0) ? ((sq + sv.z >= 0.f) ? Eq*ev.z : Fq*fv.z) : 0.f;
    float w3 = (mv.w > 0) ? ((sq + sv.w >= 0.f) ? Eq*ev.w : Fq*fv.w) : 0.f;
    float s = w0 + w1 + w2 + w3;
    #pragma unroll
    for (int o = 16; o; o >>= 1) s += __shfl_xor_sync(0xffffffffu, s, o);
    __shared__ float swarp[8];
    __shared__ float sinv;
    if ((tid & 31) == 0) swarp[tid >> 5] = s;
    __syncthreads();
    if (tid < 8) {
        float v = swarp[tid];
        #pragma unroll
        for (int o = 4; o; o >>= 1) v += __shfl_xor_sync(0xffu, v, o);
        if (tid == 0) sinv = 1.f / v;
    }
    __syncthreads();
    float inv = sinv;
    ((uint2*)g_p)[(base >> 2) + tid] =
        make_uint2(pk(w0*inv, w1*inv), pk(w2*inv, w3*inv));
}

// ---------------- bf16 MMA GEMM (m16n8k16 + ldmatrix + cp.async x4) -------------
// MODE 0: typed linear: z=which*3+t. A=g_ndr gathered via perm, K=512. C scattered.
// MODE 1: gates: z=0 -> g_rn = bf16(sigmoid(.)*nodes); z=1 -> g_z = sigmoid(.)
// MODE 2: final: out = (1-z)*nodes + z*tanh(.)
// MODE 3: GAT: h = P @ V per (dir,batch). K=1024.
#define APITCH 40
#define BPITCH 136
#define A_E (128*APITCH)       // 5120 bf16
#define B_E (32*BPITCH)        // 4352 bf16
#define STG_E (A_E + B_E)      // 9472 bf16 per stage
#define NSTG 4
#define SMEM_BYTES (NSTG*STG_E*2) // 75776 B

template<int MODE>
__global__ __launch_bounds__(512, 2) void k_mma(
    const float* __restrict__ nodes_raw,
    const float* __restrict__ bias_a, const float* __restrict__ bias_b,
    float* __restrict__ Cout)
{
    constexpr int KIT = (MODE==0) ? 16 : (MODE==3) ? 32 : 48;
    extern __shared__ bf16 smem[];
    unsigned sbase = (unsigned)__cvta_generic_to_shared(smem);

    int tid = threadIdx.x;
    int nbase = blockIdx.x * 128;
    int ar = tid >> 2, ac = tid & 3;      // A staging: row 0..127, 8-elt chunk 0..3
    int br = tid >> 4, bc = tid & 15;     // B staging: k-row 0..31, chunk 0..15

    int zed = blockIdx.z;
    int mbase = blockIdx.y * 128;
    int ge = 1 << 30;
    const bf16* Bp = nullptr;
    bf16* Cb = nullptr;
    const bf16 *pa = nullptr;                               // MODE 0/3
    const bf16 *sA0 = nullptr, *sA1 = nullptr, *sA2 = nullptr; // MODE 1/2 segs

    if (MODE == 0) {
        int t = zed % 3, which = zed / 3;
        int gs = g_group[t]; ge = g_group[t+1];
        mbase = gs + blockIdx.y * 128;
        if (mbase >= ge) return;
        Bp = g_w + (size_t)which*WSZ + (size_t)t*DD*DD;
        Cb = which ? g_node_out : g_node_in;
        int r0 = mbase + ar;
        pa = (r0 < ge) ? g_ndr + ((size_t)g_perm[r0] << 9) : nullptr;
    } else if (MODE == 1 || MODE == 2) {
        size_t o0 = (size_t)(mbase + ar) << 9;
        sA0 = g_h_in + o0;
        sA1 = g_h_out + o0;
        sA2 = (MODE == 1 ? g_ndr : g_rn) + o0;
        Bp = g_w + (size_t)((MODE == 1) ? (2 + zed) : 4) * WSZ;
    } else { // MODE 3
        int dir = zed >> 3, b = zed & 7;
        pa = g_p + ((size_t)(dir*M_TOT + (b << 10) + mbase + ar) << 10);
        Bp = (dir ? g_node_out : g_node_in) + (((size_t)(b << 10)) << 9);
        Cb = (dir ? g_h_out  : g_h_in) + (((size_t)(b << 10)) << 9);
    }

    auto issue = [&](int kt) {
        unsigned st = (unsigned)((kt % NSTG) * STG_E);
        unsigned dA = sbase + (st + ar*APITCH + ac*8) * 2;
        int col = kt*32 + ac*8;
        if (MODE == 0) {
            cpa16(dA, pa ? pa + col : (const bf16*)g_ndr, pa != nullptr);
        } else if (MODE == 3) {
            cpa16(dA, pa + col, true);
        } else {
            int seg = kt >> 4;
            int off = (kt & 15)*32 + ac*8;
            const bf16* sb = (seg == 0) ? sA0 : (seg == 1) ? sA1 : sA2;
            cpa16(dA, sb + off, true);
        }
        unsigned dB = sbase + (st + A_E + br*BPITCH + bc*8) * 2;
        cpa16(dB, Bp + (size_t)(kt*32 + br)*DD + nbase + bc*8, true);
    };

    // fragment lane decomposition
    int lane = tid & 31, wid = tid >> 5;
    int wm = (wid >> 2) * 32, wn = (wid & 3) * 32;
    int q = lane >> 3, li = lane & 7;
    int arow_f = li + (q & 1)*8;
    int acol_f = (q >> 1)*8;
    int g = lane >> 2, tg = lane & 3;

    float acc[2][4][4];
    #pragma unroll
    for (int mi = 0; mi < 2; mi++)
        #pragma unroll
        for (int ni = 0; ni < 4; ni++)
            #pragma unroll
            for (int qq = 0; qq < 4; qq++) acc[mi][ni][qq] = 0.f;

    issue(0); cpa_commit();
    issue(1); cpa_commit();
    issue(2); cpa_commit();

    for (int kt = 0; kt < KIT; kt++) {
        asm volatile("cp.async.wait_group 2;\n");
        __syncthreads();
        if (kt + 3 < KIT) issue(kt + 3);
        cpa_commit();

        unsigned As = sbase + (unsigned)((kt % NSTG) * STG_E) * 2;
        unsigned Bs = As + A_E * 2;
        #pragma unroll
        for (int ks = 0; ks < 32; ks += 16) {
            unsigned a[2][4], bfr[2][4];
            #pragma unroll
            for (int mi = 0; mi < 2; mi++)
                ldsm4(a[mi], As + ((wm + mi*16 + arow_f)*APITCH + ks + acol_f) * 2);
            #pragma unroll
            for (int n2 = 0; n2 < 2; n2++)
                ldsm4t(bfr[n2], Bs + ((ks + arow_f)*BPITCH + wn + n2*16 + acol_f) * 2);
            #pragma unroll
            for (int mi = 0; mi < 2; mi++)
                #pragma unroll
                for (int ni = 0; ni < 4; ni++)
                    mma16(acc[mi][ni], a[mi], bfr[ni>>1][(ni&1)*2], bfr[ni>>1][(ni&1)*2+1]);
        }
    }

    // ---- epilogue
    #pragma unroll
    for (int mi = 0; mi < 2; mi++) {
        int rA = mbase + wm + mi*16 + g;
        int rB = rA + 8;
        int pA = rA, pB = rB;
        if (MODE == 0) {
            pA = (rA < ge) ? g_perm[rA] : -1;
            pB = (rB < ge) ? g_perm[rB] : -1;
        }
        #pragma unroll
        for (int ni = 0; ni < 4; ni++) {
            int col = nbase + wn + ni*8 + 2*tg;
            float c0 = acc[mi][ni][0], c1 = acc[mi][ni][1];
            float c2 = acc[mi][ni][2], c3 = acc[mi][ni][3];
            if (MODE == 0) {
                if (pA >= 0) *(unsigned*)&Cb[((size_t)pA << 9) + col] = pk(c0, c1);
                if (pB >= 0) *(unsigned*)&Cb[((size_t)pB << 9) + col] = pk(c2, c3);
            } else if (MODE == 1) {
                size_t oA = ((size_t)pA << 9) + col, oB = ((size_t)pB << 9) + col;
                float2 bb = *(const float2*)&((zed == 0) ? bias_a : bias_b)[col];
                float s0 = 1.f/(1.f + __expf(-(c0 + bb.x)));
                float s1 = 1.f/(1.f + __expf(-(c1 + bb.y)));
                float s2 = 1.f/(1.f + __expf(-(c2 + bb.x)));
                float s3 = 1.f/(1.f + __expf(-(c3 + bb.y)));
                if (zed == 0) {
                    float2 nA = *(const float2*)&nodes_raw[oA];
                    float2 nB = *(const float2*)&nodes_raw[oB];
                    *(unsigned*)&g_rn[oA] = pk(s0*nA.x, s1*nA.y);
                    *(unsigned*)&g_rn[oB] = pk(s2*nB.x, s3*nB.y);
                } else {
                    *(float2*)&g_z[oA] = make_float2(s0, s1);
                    *(float2*)&g_z[oB] = make_float2(s2, s3);
                }
            } else if (MODE == 2) {
                float2 bb = *(const float2*)&bias_a[col];
                size_t oA = ((size_t)pA << 9) + col, oB = ((size_t)pB << 9) + col;
                float2 zA = *(const float2*)&g_z[oA], zB = *(const float2*)&g_z[oB];
                float2 nA = *(const float2*)&nodes_raw[oA], nB = *(const float2*)&nodes_raw[oB];
                float h0 = tanhf(c0 + bb.x), h1 = tanhf(c1 + bb.y);
                float h2 = tanhf(c2 + bb.x), h3 = tanhf(c3 + bb.y);
                *(float2*)&Cout[oA] = make_float2((1.f-zA.x)*nA.x + zA.x*h0,
                                                  (1.f-zA.y)*nA.y + zA.y*h1);
                *(float2*)&Cout[oB] = make_float2((1.f-zB.x)*nB.x + zB.x*h2,
                                                  (1.f-zB.y)*nB.y + zB.y*h3);
            } else { // MODE 3
                *(unsigned*)&Cb[((size_t)pA << 9) + col] = pk(c0, c1);
                *(unsigned*)&Cb[((size_t)pB << 9) + col] = pk(c2, c3);
            }
        }
    }
}

// ---------------- launch ----------------
extern "C" void kernel_launch(void* const* d_in, const int* in_sizes, int n_in,
                              void* d_out, int out_size)
{
    const float* nodes  = (const float*)d_in[0];
    const int*   mask   = (const int*)  d_in[1];
    const int*   ntw    = (const int*)  d_in[2];
    const float* W_in   = (const float*)d_in[3];
    const float* W_out  = (const float*)d_in[4];
    const float* a_in_q = (const float*)d_in[5];
    const float* a_in_v = (const float*)d_in[6];
    const float* a_out_q= (const float*)d_in[7];
    const float* a_out_v= (const float*)d_in[8];
    const float* W_r    = (const float*)d_in[9];
    const float* b_r    = (const float*)d_in[10];
    const float* W_z    = (const float*)d_in[11];
    const float* b_z    = (const float*)d_in[12];
    const float* W_t    = (const float*)d_in[13];
    const float* b_t    = (const float*)d_in[14];
    float* out = (float*)d_out;

    cudaFuncSetAttribute(k_mma<0>, cudaFuncAttributeMaxDynamicSharedMemorySize, SMEM_BYTES);
    cudaFuncSetAttribute(k_mma<1>, cudaFuncAttributeMaxDynamicSharedMemorySize, SMEM_BYTES);
    cudaFuncSetAttribute(k_mma<2>, cudaFuncAttributeMaxDynamicSharedMemorySize, SMEM_BYTES);
    cudaFuncSetAttribute(k_mma<3>, cudaFuncAttributeMaxDynamicSharedMemorySize, SMEM_BYTES);

    k_prep<<<1, 1024>>>(ntw);
    k_zero<<<2048, 256>>>();
    CvtSrcs cs = { nodes, W_in, W_out, W_r, W_z, W_t };
    k_cvt_all<<<7936, 256>>>(cs);
    k_mma<0><<<dim3(4, 64, 6), 512, SMEM_BYTES>>>(nodes, nullptr, nullptr, nullptr);
    k_dots<<<M_TOT, 128>>>(nodes, a_in_q, a_in_v, a_out_q, a_out_v);
    k_p<<<dim3(M_TOT, 2), 256>>>(mask);
    k_mma<3><<<dim3(4, 8, 16), 512, SMEM_BYTES>>>(nodes, nullptr, nullptr, nullptr);
    k_mma<1><<<dim3(4, 64, 2), 512, SMEM_BYTES>>>(nodes, b_r, b_z, nullptr);
    k_mma<2><<<dim3(4, 64, 1), 512, SMEM_BYTES>>>(nodes, b_t, nullptr, out);
}

// round 16
// speedup vs baseline: 1.6414x; 1.0416x over previous
#include <cuda_runtime.h>
#include <cuda_bf16.h>
#include <math.h>

#define M_TOT 8192
#define DD 512
#define WSZ (3*512*512)   // elements per weight blob

typedef __nv_bfloat16 bf16;

// ---------------- scratch ----------------
__device__ int   g_perm[M_TOT];
__device__ int   g_group[4];
__device__ bf16  g_ndr[M_TOT*DD];        // bf16 nodes
__device__ bf16  g_node_in [M_TOT*DD];
__device__ bf16  g_node_out[M_TOT*DD];
__device__ bf16  g_h_in [M_TOT*DD];
__device__ bf16  g_h_out[M_TOT*DD];
__device__ bf16  g_rn[M_TOT*DD];         // bf16 r*nodes
__device__ float g_z[M_TOT*DD];          // fp32
__device__ bf16  g_w[5*WSZ];             // bf16 W_in,W_out,W_r,W_z,W_t
__device__ bf16  g_p[2*M_TOT*1024];      // bf16 probs (32MB)
__device__ float g_sq[2*M_TOT];
__device__ float g_sv[2*M_TOT];
__device__ float g_eq[2*M_TOT];
__device__ float g_fq[2*M_TOT];
__device__ float g_ev[2*M_TOT];
__device__ float g_fv[2*M_TOT];

// ---------------- helpers ----------------
__device__ __forceinline__ unsigned pk(float a, float b) {
    __nv_bfloat162 t = __floats2bfloat162_rn(a, b);
    return *(unsigned*)&t;
}
__device__ __forceinline__ void mma16(float* c, const unsigned* a, unsigned b0, unsigned b1) {
    asm volatile(
        "mma.sync.aligned.m16n8k16.row.col.f32.bf16.bf16.f32 "
        "{%0,%1,%2,%3}, {%4,%5,%6,%7}, {%8,%9}, {%0,%1,%2,%3};\n"
        : "+f"(c[0]), "+f"(c[1]), "+f"(c[2]), "+f"(c[3])
        : "r"(a[0]), "r"(a[1]), "r"(a[2]), "r"(a[3]), "r"(b0), "r"(b1));
}
__device__ __forceinline__ void ldsm4(unsigned* r, unsigned addr) {
    asm volatile("ldmatrix.sync.aligned.m8n8.x4.shared.b16 {%0,%1,%2,%3}, [%4];"
        : "=r"(r[0]), "=r"(r[1]), "=r"(r[2]), "=r"(r[3]) : "r"(addr));
}
__device__ __forceinline__ void ldsm4t(unsigned* r, unsigned addr) {
    asm volatile("ldmatrix.sync.aligned.m8n8.x4.trans.shared.b16 {%0,%1,%2,%3}, [%4];"
        : "=r"(r[0]), "=r"(r[1]), "=r"(r[2]), "=r"(r[3]) : "r"(addr));
}
__device__ __forceinline__ void cpa16(unsigned dst, const void* src, bool v) {
    int sz = v ? 16 : 0;
    asm volatile("cp.async.cg.shared.global [%0], [%1], 16, %2;\n"
                 :: "r"(dst), "l"(src), "r"(sz));
}
__device__ __forceinline__ void cpa_commit() {
    asm volatile("cp.async.commit_group;\n");
}

// ---------------- prep ----------------
__global__ void k_prep(const int* __restrict__ ntw)
{
    __shared__ int s_flag;
    __shared__ int s_cnt[1024*3];
    __shared__ int s_tot[3];
    int tid = threadIdx.x;
    if (tid == 0) s_flag = 0;
    __syncthreads();
    int bad = 0;
    for (int i = tid; i < 4096; i += 1024)
        if (ntw[2*i+1] != 0) bad = 1;
    if (bad) atomicOr(&s_flag, 1);
    __syncthreads();
    int is64 = (s_flag == 0);

    int tv[8];
    int c0 = 0, c1 = 0, c2 = 0;
    for (int k = 0; k < 8; k++) {
        int idx = tid*8 + k;
        int v = is64 ? ntw[2*idx] : ntw[idx];
        int t = (v >= 2 && v <= 4) ? (v - 2) : -1;
        tv[k] = t;
        if (t == 0) c0++; else if (t == 1) c1++; else if (t == 2) c2++;
    }
    s_cnt[tid*3+0] = c0; s_cnt[tid*3+1] = c1; s_cnt[tid*3+2] = c2;
    __syncthreads();
    if (tid < 3) {
        int run = 0;
        for (int i = 0; i < 1024; i++) {
            int c = s_cnt[i*3+tid]; s_cnt[i*3+tid] = run; run += c;
        }
        s_tot[tid] = run;
    }
    __syncthreads();
    if (tid == 0) {
        g_group[0] = 0;
        g_group[1] = s_tot[0];
        g_group[2] = s_tot[0] + s_tot[1];
        g_group[3] = s_tot[0] + s_tot[1] + s_tot[2];
    }
    int b0 = s_cnt[tid*3+0];
    int b1 = s_tot[0] + s_cnt[tid*3+1];
    int b2 = s_tot[0] + s_tot[1] + s_cnt[tid*3+2];
    for (int k = 0; k < 8; k++) {
        int idx = tid*8 + k;
        int t = tv[k];
        if (t == 0)      g_perm[b0++] = idx;
        else if (t == 1) g_perm[b1++] = idx;
        else if (t == 2) g_perm[b2++] = idx;
    }
}

__global__ void k_zero()   // zero bf16 node_in/out
{
    int i = blockIdx.x * blockDim.x + threadIdx.x;
    float4 zz = make_float4(0.f, 0.f, 0.f, 0.f);
    ((float4*)g_node_in)[i]  = zz;
    ((float4*)g_node_out)[i] = zz;
}

// ---------------- convert nodes + 5 weight blobs to bf16 ----------------
struct CvtSrcs { const float* nodes; const float* w0; const float* w1;
                 const float* w2; const float* w3; const float* w4; };
__global__ void k_cvt_all(CvtSrcs s)
{
    int i = blockIdx.x * blockDim.x + threadIdx.x;   // float4 index
    const int NF4 = M_TOT*DD/4;        // 1048576
    const int WF4 = WSZ/4;             // 196608
    if (i < NF4) {
        float4 v = ((const float4*)s.nodes)[i];
        ((uint2*)g_ndr)[i] = make_uint2(pk(v.x, v.y), pk(v.z, v.w));
    } else {
        int j = i - NF4;
        int wi = j / WF4, off = j % WF4;
        const float* src = (wi==0)?s.w0:(wi==1)?s.w1:(wi==2)?s.w2:(wi==3)?s.w3:s.w4;
        float4 v = ((const float4*)src)[off];
        ((uint2*)g_w)[j] = make_uint2(pk(v.x, v.y), pk(v.z, v.w));
    }
}

// ---------------- per-row dots + factored exps ----------------
__device__ __forceinline__ float dot4(float4 a, float4 b) {
    return a.x*b.x + a.y*b.y + a.z*b.z + a.w*b.w;
}
__device__ __forceinline__ float dotb(uint2 u, float4 b) {
    float2 f0 = __bfloat1622float2(*(__nv_bfloat162*)&u.x);
    float2 f1 = __bfloat1622float2(*(__nv_bfloat162*)&u.y);
    return f0.x*b.x + f0.y*b.y + f1.x*b.z + f1.y*b.w;
}
__global__ void k_dots(const float* __restrict__ nodes,
    const float* __restrict__ aqi, const float* __restrict__ avi,
    const float* __restrict__ aqo, const float* __restrict__ avo)
{
    int row = blockIdx.x, tid = threadIdx.x;
    size_t off = ((size_t)row << 9) + tid*4;
    int d = tid*4;
    float4 nv = *(const float4*)(nodes + off);
    uint2 ni = *(const uint2*)(g_node_in + off);
    uint2 no = *(const uint2*)(g_node_out + off);
    float s0 = dot4(nv, *(const float4*)(aqi + d));
    float s1 = dotb(ni, *(const float4*)(avi + d));
    float s2 = dot4(nv, *(const float4*)(aqo + d));
    float s3 = dotb(no, *(const float4*)(avo + d));
    #pragma unroll
    for (int o2 = 16; o2; o2 >>= 1) {
        s0 += __shfl_down_sync(0xffffffffu, s0, o2);
        s1 += __shfl_down_sync(0xffffffffu, s1, o2);
        s2 += __shfl_down_sync(0xffffffffu, s2, o2);
        s3 += __shfl_down_sync(0xffffffffu, s3, o2);
    }
    __shared__ float sm[4][4];
    int w = tid >> 5, l = tid & 31;
    if (l == 0) { sm[w][0]=s0; sm[w][1]=s1; sm[w][2]=s2; sm[w][3]=s3; }
    __syncthreads();
    if (tid == 0) {
        float r0=0,r1=0,r2=0,r3=0;
        #pragma unroll
        for (int i = 0; i < 4; i++) { r0+=sm[i][0]; r1+=sm[i][1]; r2+=sm[i][2]; r3+=sm[i][3]; }
        g_sq[row] = r0; g_sv[row] = r1;
        g_sq[M_TOT+row] = r2; g_sv[M_TOT+row] = r3;
        g_eq[row] = __expf(r0);        g_fq[row] = __expf(0.2f*r0);
        g_ev[row] = __expf(r1);        g_fv[row] = __expf(0.2f*r1);
        g_eq[M_TOT+row] = __expf(r2);  g_fq[M_TOT+row] = __expf(0.2f*r2);
        g_ev[M_TOT+row] = __expf(r3);  g_fv[M_TOT+row] = __expf(0.2f*r3);
    }
}

// ---------------- P: normalized attention probabilities (bf16) ----------------
__global__ __launch_bounds__(256) void k_p(const int* __restrict__ mask)
{
    int row = blockIdx.x, dir = blockIdx.y;
    int b = row >> 10;
    int tid = threadIdx.x;
    size_t base = ((size_t)(dir*M_TOT + row)) << 10;
    int gi = dir*M_TOT + row;
    float sq = g_sq[gi], Eq = g_eq[gi], Fq = g_fq[gi];
    int jb = dir*M_TOT + (b << 10);
    int4   mv = ((const int4*)(mask + base))[tid];
    float4 sv = ((const float4*)(g_sv + jb))[tid];
    float4 ev = ((const float4*)(g_ev + jb))[tid];
    float4 fv = ((const float4*)(g_fv + jb))[tid];
    float w0 = (mv.x > 0) ? ((sq + sv.x >= 0.f) ? Eq*ev.x : Fq*fv.x) : 0.f;
    float w1 = (mv.y > 0) ? ((sq + sv.y >= 0.f) ? Eq*ev.y : Fq*fv.y) : 0.f;
    float w2 = (mv.z > 0) ? ((sq + sv.z >= 0.f) ? Eq*ev.z : Fq*fv.z) : 0.f;
    float w3 = (mv.w > 0) ? ((sq + sv.w >= 0.f) ? Eq*ev.w : Fq*fv.w) : 0.f;
    float s = w0 + w1 + w2 + w3;
    #pragma unroll
    for (int o = 16; o; o >>= 1) s += __shfl_xor_sync(0xffffffffu, s, o);
    __shared__ float swarp[8];
    __shared__ float sinv;
    if ((tid & 31) == 0) swarp[tid >> 5] = s;
    __syncthreads();
    if (tid < 8) {
        float v = swarp[tid];
        #pragma unroll
        for (int o = 4; o; o >>= 1) v += __shfl_xor_sync(0xffu, v, o);
        if (tid == 0) sinv = 1.f / v;
    }
    __syncthreads();
    float inv = sinv;
    ((uint2*)g_p)[(base >> 2) + tid] =
        make_uint2(pk(w0*inv, w1*inv), pk(w2*inv, w3*inv));
}

// ---------------- bf16 MMA GEMM: 256 threads, warp tile 32x64 -------------------
// MODE 0: typed linear: z=which*3+t. A=g_ndr gathered via perm, K=512. C scattered.
// MODE 1: gates: z=0 -> g_rn = bf16(sigmoid(.)*nodes); z=1 -> g_z = sigmoid(.)
// MODE 2: final: out = (1-z)*nodes + z*tanh(.)
// MODE 3: GAT: h = P @ V per (dir,batch). K=1024.
#define APITCH 40
#define BPITCH 136
#define A_E (128*APITCH)       // 5120 bf16
#define B_E (32*BPITCH)        // 4352 bf16
#define STG_E (A_E + B_E)      // 9472 bf16 per stage
#define NSTG 4
#define SMEM_BYTES (NSTG*STG_E*2) // 75776 B

template<int MODE>
__global__ __launch_bounds__(256, 2) void k_mma(
    const float* __restrict__ nodes_raw,
    const float* __restrict__ bias_a, const float* __restrict__ bias_b,
    float* __restrict__ Cout)
{
    constexpr int KIT = (MODE==0) ? 16 : (MODE==3) ? 32 : 48;
    extern __shared__ bf16 smem[];
    unsigned sbase = (unsigned)__cvta_generic_to_shared(smem);

    int tid = threadIdx.x;
    int nbase = blockIdx.x * 128;
    int ar = tid >> 2, ac = tid & 3;      // A staging: rows ar, ar+64; chunk ac
    int br = tid >> 4, bc = tid & 15;     // B staging: k-rows br, br+16

    int zed = blockIdx.z;
    int mbase = blockIdx.y * 128;
    int ge = 1 << 30;
    const bf16* Bp = nullptr;
    bf16* Cb = nullptr;
    const bf16 *pa0 = nullptr, *pa1 = nullptr;                 // MODE 0/3
    const bf16 *sA0 = nullptr, *sA1 = nullptr, *sA2 = nullptr; // MODE 1/2 segs

    if (MODE == 0) {
        int t = zed % 3, which = zed / 3;
        int gs = g_group[t]; ge = g_group[t+1];
        mbase = gs + blockIdx.y * 128;
        if (mbase >= ge) return;
        Bp = g_w + (size_t)which*WSZ + (size_t)t*DD*DD;
        Cb = which ? g_node_out : g_node_in;
        int r0 = mbase + ar, r1 = r0 + 64;
        pa0 = (r0 < ge) ? g_ndr + ((size_t)g_perm[r0] << 9) : nullptr;
        pa1 = (r1 < ge) ? g_ndr + ((size_t)g_perm[r1] << 9) : nullptr;
    } else if (MODE == 1 || MODE == 2) {
        size_t o0 = (size_t)(mbase + ar) << 9;
        sA0 = g_h_in + o0;
        sA1 = g_h_out + o0;
        sA2 = (MODE == 1 ? g_ndr : g_rn) + o0;
        Bp = g_w + (size_t)((MODE == 1) ? (2 + zed) : 4) * WSZ;
    } else { // MODE 3
        int dir = zed >> 3, b = zed & 7;
        pa0 = g_p + ((size_t)(dir*M_TOT + (b << 10) + mbase + ar) << 10);
        pa1 = pa0 + ((size_t)64 << 10);
        Bp = (dir ? g_node_out : g_node_in) + (((size_t)(b << 10)) << 9);
        Cb = (dir ? g_h_out  : g_h_in) + (((size_t)(b << 10)) << 9);
    }

    auto issue = [&](int kt) {
        unsigned st = (unsigned)((kt % NSTG) * STG_E);
        unsigned dA0 = sbase + (st + ar*APITCH + ac*8) * 2;
        unsigned dA1 = dA0 + 64*APITCH*2;
        int col = kt*32 + ac*8;
        if (MODE == 0) {
            cpa16(dA0, pa0 ? pa0 + col : (const bf16*)g_ndr, pa0 != nullptr);
            cpa16(dA1, pa1 ? pa1 + col : (const bf16*)g_ndr, pa1 != nullptr);
        } else if (MODE == 3) {
            cpa16(dA0, pa0 + col, true);
            cpa16(dA1, pa1 + col, true);
        } else {
            int seg = kt >> 4;
            int off = (kt & 15)*32 + ac*8;
            const bf16* sb = (seg == 0) ? sA0 : (seg == 1) ? sA1 : sA2;
            cpa16(dA0, sb + off, true);
            cpa16(dA1, sb + off + ((size_t)64 << 9), true);
        }
        unsigned dB0 = sbase + (st + A_E + br*BPITCH + bc*8) * 2;
        unsigned dB1 = dB0 + 16*BPITCH*2;
        const bf16* sB = Bp + (size_t)(kt*32 + br)*DD + nbase + bc*8;
        cpa16(dB0, sB, true);
        cpa16(dB1, sB + (size_t)16*DD, true);
    };

    // fragment lane decomposition: 8 warps in 4m x 2n, warp tile 32x64
    int lane = tid & 31, wid = tid >> 5;
    int wm = (wid >> 1) * 32, wn = (wid & 1) * 64;
    int q = lane >> 3, li = lane & 7;
    int arow_f = li + (q & 1)*8;
    int acol_f = (q >> 1)*8;
    int g = lane >> 2, tg = lane & 3;

    float acc[2][8][4];
    #pragma unroll
    for (int mi = 0; mi < 2; mi++)
        #pragma unroll
        for (int ni = 0; ni < 8; ni++)
            #pragma unroll
            for (int qq = 0; qq < 4; qq++) acc[mi][ni][qq] = 0.f;

    issue(0); cpa_commit();
    issue(1); cpa_commit();
    issue(2); cpa_commit();

    for (int kt = 0; kt < KIT; kt++) {
        asm volatile("cp.async.wait_group 2;\n");
        __syncthreads();
        if (kt + 3 < KIT) issue(kt + 3);
        cpa_commit();

        unsigned As = sbase + (unsigned)((kt % NSTG) * STG_E) * 2;
        unsigned Bs = As + A_E * 2;
        #pragma unroll
        for (int ks = 0; ks < 32; ks += 16) {
            unsigned a[2][4], bfr[4][4];
            #pragma unroll
            for (int mi = 0; mi < 2; mi++)
                ldsm4(a[mi], As + ((wm + mi*16 + arow_f)*APITCH + ks + acol_f) * 2);
            #pragma unroll
            for (int n2 = 0; n2 < 4; n2++)
                ldsm4t(bfr[n2], Bs + ((ks + arow_f)*BPITCH + wn + n2*16 + acol_f) * 2);
            #pragma unroll
            for (int mi = 0; mi < 2; mi++)
                #pragma unroll
                for (int ni = 0; ni < 8; ni++)
                    mma16(acc[mi][ni], a[mi], bfr[ni>>1][(ni&1)*2], bfr[ni>>1][(ni&1)*2+1]);
        }
    }

    // ---- epilogue
    #pragma unroll
    for (int mi = 0; mi < 2; mi++) {
        int rA = mbase + wm + mi*16 + g;
        int rB = rA + 8;
        int pA = rA, pB = rB;
        if (MODE == 0) {
            pA = (rA < ge) ? g_perm[rA] : -1;
            pB = (rB < ge) ? g_perm[rB] : -1;
        }
        #pragma unroll
        for (int ni = 0; ni < 8; ni++) {
            int col = nbase + wn + ni*8 + 2*tg;
            float c0 = acc[mi][ni][0], c1 = acc[mi][ni][1];
            float c2 = acc[mi][ni][2], c3 = acc[mi][ni][3];
            if (MODE == 0) {
                if (pA >= 0) *(unsigned*)&Cb[((size_t)pA << 9) + col] = pk(c0, c1);
                if (pB >= 0) *(unsigned*)&Cb[((size_t)pB << 9) + col] = pk(c2, c3);
            } else if (MODE == 1) {
                size_t oA = ((size_t)pA << 9) + col, oB = ((size_t)pB << 9) + col;
                float2 bb = *(const float2*)&((zed == 0) ? bias_a : bias_b)[col];
                float s0 = 1.f/(1.f + __expf(-(c0 + bb.x)));
                float s1 = 1.f/(1.f + __expf(-(c1 + bb.y)));
                float s2 = 1.f/(1.f + __expf(-(c2 + bb.x)));
                float s3 = 1.f/(1.f + __expf(-(c3 + bb.y)));
                if (zed == 0) {
                    float2 nA = *(const float2*)&nodes_raw[oA];
                    float2 nB = *(const float2*)&nodes_raw[oB];
                    *(unsigned*)&g_rn[oA] = pk(s0*nA.x, s1*nA.y);
                    *(unsigned*)&g_rn[oB] = pk(s2*nB.x, s3*nB.y);
                } else {
                    *(float2*)&g_z[oA] = make_float2(s0, s1);
                    *(float2*)&g_z[oB] = make_float2(s2, s3);
                }
            } else if (MODE == 2) {
                float2 bb = *(const float2*)&bias_a[col];
                size_t oA = ((size_t)pA << 9) + col, oB = ((size_t)pB << 9) + col;
                float2 zA = *(const float2*)&g_z[oA], zB = *(const float2*)&g_z[oB];
                float2 nA = *(const float2*)&nodes_raw[oA], nB = *(const float2*)&nodes_raw[oB];
                float h0 = tanhf(c0 + bb.x), h1 = tanhf(c1 + bb.y);
                float h2 = tanhf(c2 + bb.x), h3 = tanhf(c3 + bb.y);
                *(float2*)&Cout[oA] = make_float2((1.f-zA.x)*nA.x + zA.x*h0,
                                                  (1.f-zA.y)*nA.y + zA.y*h1);
                *(float2*)&Cout[oB] = make_float2((1.f-zB.x)*nB.x + zB.x*h2,
                                                  (1.f-zB.y)*nB.y + zB.y*h3);
            } else { // MODE 3
                *(unsigned*)&Cb[((size_t)pA << 9) + col] = pk(c0, c1);
                *(unsigned*)&Cb[((size_t)pB << 9) + col] = pk(c2, c3);
            }
        }
    }
}

// ---------------- launch ----------------
extern "C" void kernel_launch(void* const* d_in, const int* in_sizes, int n_in,
                              void* d_out, int out_size)
{
    const float* nodes  = (const float*)d_in[0];
    const int*   mask   = (const int*)  d_in[1];
    const int*   ntw    = (const int*)  d_in[2];
    const float* W_in   = (const float*)d_in[3];
    const float* W_out  = (const float*)d_in[4];
    const float* a_in_q = (const float*)d_in[5];
    const float* a_in_v = (const float*)d_in[6];
    const float* a_out_q= (const float*)d_in[7];
    const float* a_out_v= (const float*)d_in[8];
    const float* W_r    = (const float*)d_in[9];
    const float* b_r    = (const float*)d_in[10];
    const float* W_z    = (const float*)d_in[11];
    const float* b_z    = (const float*)d_in[12];
    const float* W_t    = (const float*)d_in[13];
    const float* b_t    = (const float*)d_in[14];
    float* out = (float*)d_out;

    cudaFuncSetAttribute(k_mma<0>, cudaFuncAttributeMaxDynamicSharedMemorySize, SMEM_BYTES);
    cudaFuncSetAttribute(k_mma<1>, cudaFuncAttributeMaxDynamicSharedMemorySize, SMEM_BYTES);
    cudaFuncSetAttribute(k_mma<2>, cudaFuncAttributeMaxDynamicSharedMemorySize, SMEM_BYTES);
    cudaFuncSetAttribute(k_mma<3>, cudaFuncAttributeMaxDynamicSharedMemorySize, SMEM_BYTES);

    k_prep<<<1, 1024>>>(ntw);
    k_zero<<<2048, 256>>>();
    CvtSrcs cs = { nodes, W_in, W_out, W_r, W_z, W_t };
    k_cvt_all<<<7936, 256>>>(cs);
    k_mma<0><<<dim3(4, 64, 6), 256, SMEM_BYTES>>>(nodes, nullptr, nullptr, nullptr);
    k_dots<<<M_TOT, 128>>>(nodes, a_in_q, a_in_v, a_out_q, a_out_v);
    k_p<<<dim3(M_TOT, 2), 256>>>(mask);
    k_mma<3><<<dim3(4, 8, 16), 256, SMEM_BYTES>>>(nodes, nullptr, nullptr, nullptr);
    k_mma<1><<<dim3(4, 64, 2), 256, SMEM_BYTES>>>(nodes, b_r, b_z, nullptr);
    k_mma<2><<<dim3(4, 64, 1), 256, SMEM_BYTES>>>(nodes, b_t, nullptr, out);
}